// round 7
// baseline (speedup 1.0000x reference)
#include <cuda_runtime.h>

// 16-qubit, 2-layer BasicEntangler QNN — branchless transfer-matrix closed form.
// FINAL variant (best measured: 6.53 us end-to-end; single-launch floor).
//
// Derivation (verified rounds 1-3 against the state-vector implementation):
//   All generators are X-type and commute. CNOT rings commute to the ends:
//   <Z_w> = <0| Prod_{j in A_w} exp(i theta_j X_{m_j}) |0>,
//   masks m: {w} with phi_w = x_w + W0_w;  b_0={0,1}, b_v={v,v+1} (v=1..14),
//   b_15={0,1,15} (= F^{-1} e_v);  S = R_w = row w of F^2 (R_MASK).
//   XOR-zero subset sum -> 2-state chain DP over wires; outer var t15 gives
//   two chains, one per lane (lane^16 = partner), combined with one shfl.
//
// Perf note: body ~0.5us; remaining time is launch overhead + graph replay.
// Rounds 4-6 varied instruction count 2x with <5% effect — at the floor.

#define NQ 16

__constant__ unsigned int R_MASK[16] = {
    0xAAABu, 0xFFFDu, 0xFFFAu, 0xFFF5u, 0xFFEAu, 0xFFD5u, 0xFFAAu, 0xFF55u,
    0xFEAAu, 0xFD55u, 0xFAAAu, 0xF555u, 0xEAAAu, 0xD555u, 0xAAAAu, 0x5555u
};

__global__ void __launch_bounds__(32)
qnn_final(const float* __restrict__ x, const float* __restrict__ wts,
          float* __restrict__ out) {
    __shared__ float cph[NQ], sph[NQ], cth[NQ], sth[NQ];

    const int lane = threadIdx.x;
    const int w    = lane & 15;          // output wire
    const bool isB = lane >= 16;         // chain select (t15 = 1)
    const int b    = blockIdx.x;         // sample (one warp per sample)

    // prologue: halves of the warp compute phi- and theta-sincos in parallel
    if (!isB) {
        float s, c;
        __sincosf(x[b * NQ + w] + wts[w], &s, &c);   // phi = x + W0
        cph[w] = c; sph[w] = s;
    } else {
        float s, c;
        __sincosf(wts[NQ + w], &s, &c);              // layer-1 theta
        cth[w] = c; sth[w] = s;
    }
    __syncwarp();

    const unsigned S = R_MASK[w];

    // ---- init (step v=0); chain-B v==1 u-swap folded into amp0<->amp1 ----
    float a0x, a0y, a1x, a1y;
    {
        const bool ab = (S ^ (S >> 1)) & 1;          // b_0={0,1}
        const bool ae = S & 1;
        const float wt0r = ab ? cth[0] : 1.f;
        const float wt1i = ab ? sth[0] : 0.f;
        const float wm0r = ae ? cph[0] : 1.f;
        const float wm1i = ae ? sph[0] : 0.f;
        const float q0 = (isB ? wt1i : wt0r) * wm0r;
        const float q1 = (isB ? wt0r : -wt1i) * wm1i;
        a0x = isB ? 0.f : q0;  a0y = isB ? q0 : 0.f;
        a1x = isB ? 0.f : q1;  a1y = isB ? q1 : 0.f;
    }

    // ---- steps v=1..14: depth-2 recurrence, P = wt (x) wm precomputed ----
#pragma unroll
    for (int v = 1; v <= 14; v++) {
        const bool ab = ((S >> v) ^ (S >> (v + 1))) & 1;
        const bool ae = (S >> v) & 1;
        const float wt0r = ab ? cth[v] : 1.f;
        const float wt1i = ab ? sth[v] : 0.f;
        const float wm0r = ae ? cph[v] : 1.f;
        const float wm1i = ae ? sph[v] : 0.f;
        const float P00 = wt0r * wm0r;
        const float P01 = wt0r * wm1i;
        const float P10 = wt1i * wm0r;
        const float P11 = wt1i * wm1i;
        const float n0x =  P00 * a0x - P01 * a1y;
        const float n0y =  P00 * a0y + P01 * a1x;
        const float n1x = -P10 * a1y - P11 * a0x;
        const float n1y =  P10 * a1x - P11 * a0y;
        a0x = n0x; a0y = n0y; a1x = n1x; a1y = n1y;
    }

    // ---- close (mask bit 15), per-chain component select ----
    float val;
    {
        const bool ae = (S >> 15) & 1;
        const float wm0r = ae ? cph[15] : 1.f;
        const float wm1i = ae ? sph[15] : 0.f;
        const float r0 = isB ? wm1i : wm0r;
        const float r1 = isB ? wm0r : -wm1i;
        val = a0x * r0 + a1y * r1;       // A: resAx ; B: resBy
    }

    // combine chains: lane<16 holds A, partner lane^16 holds B
    const float other = __shfl_xor_sync(0xFFFFFFFFu, val, 16);
    if (!isB) {
        const bool ab15 = (S ^ (S >> 1) ^ (S >> 15)) & 1;   // b_15={0,1,15}
        const float w150r = ab15 ? cth[15] : 1.f;
        const float w151i = ab15 ? sth[15] : 0.f;
        out[b * NQ + w] = w150r * val - w151i * other;
    }
}

extern "C" void kernel_launch(void* const* d_in, const int* in_sizes, int n_in,
                              void* d_out, int out_size) {
    const float* x   = (const float*)d_in[0];   // (32,16)
    const float* wts = (const float*)d_in[1];   // (2,16)
    if (n_in >= 2 && in_sizes[0] == 32 && in_sizes[1] == 512) {
        const float* tmp = x; x = wts; wts = tmp;  // defensive order swap
    }
    float* out = (float*)d_out;                 // (32,16) float32

    qnn_final<<<32, 32>>>(x, wts, out);
}

// round 8
// speedup vs baseline: 1.0337x; 1.0337x over previous
#include <cuda_runtime.h>

// 16-qubit, 2-layer BasicEntangler QNN — branchless transfer-matrix closed form.
// Algebra verified rounds 1-3 (masks R_MASK = rows of F^2; chain masks b_v).
//   <Z_{R_w}> = <0| Prod_j exp(i theta_j X_{m_j}) |0>  ->  2-state chain DP,
//   one chain per lane (lane^16 = t15 partner), depth-2 P-product recurrence,
//   shfl combine.
// R7: pack 32 warps into 4 CTAs (8 warps/CTA, one sample per warp, private
// smem slice per warp, warp-local sync only) — tests whether per-CTA schedule
// + cold-I$ cost across 32 SMs is the residual overhead.

#define NQ 16
#define WARPS_PER_CTA 8

__constant__ unsigned int R_MASK[16] = {
    0xAAABu, 0xFFFDu, 0xFFFAu, 0xFFF5u, 0xFFEAu, 0xFFD5u, 0xFFAAu, 0xFF55u,
    0xFEAAu, 0xFD55u, 0xFAAAu, 0xF555u, 0xEAAAu, 0xD555u, 0xAAAAu, 0x5555u
};

__global__ void __launch_bounds__(32 * WARPS_PER_CTA)
qnn_tm7(const float* __restrict__ x, const float* __restrict__ wts,
        float* __restrict__ out) {
    // per-warp private slices: [warp][wire]
    __shared__ float cph[WARPS_PER_CTA][NQ], sph[WARPS_PER_CTA][NQ];
    __shared__ float cth[WARPS_PER_CTA][NQ], sth[WARPS_PER_CTA][NQ];

    const int tid  = threadIdx.x;
    const int wp   = tid >> 5;                       // warp in CTA
    const int lane = tid & 31;
    const int w    = lane & 15;                      // output wire
    const bool isB = lane >= 16;                     // chain select (t15 = 1)
    const int b    = blockIdx.x * WARPS_PER_CTA + wp; // sample (one per warp)

    // prologue: halves of each warp compute phi- and theta-sincos in parallel
    if (!isB) {
        float s, c;
        __sincosf(x[b * NQ + w] + wts[w], &s, &c);   // phi = x + W0
        cph[wp][w] = c; sph[wp][w] = s;
    } else {
        float s, c;
        __sincosf(wts[NQ + w], &s, &c);              // layer-1 theta
        cth[wp][w] = c; sth[wp][w] = s;
    }
    __syncwarp();

    const unsigned S = R_MASK[w];
    const float* cp = cph[wp];
    const float* sp = sph[wp];
    const float* ct = cth[wp];
    const float* st = sth[wp];

    // ---- init (step v=0); chain-B v==1 u-swap folded into amp0<->amp1 ----
    float a0x, a0y, a1x, a1y;
    {
        const bool ab = (S ^ (S >> 1)) & 1;          // b_0={0,1}
        const bool ae = S & 1;
        const float wt0r = ab ? ct[0] : 1.f;
        const float wt1i = ab ? st[0] : 0.f;
        const float wm0r = ae ? cp[0] : 1.f;
        const float wm1i = ae ? sp[0] : 0.f;
        const float q0 = (isB ? wt1i : wt0r) * wm0r;
        const float q1 = (isB ? wt0r : -wt1i) * wm1i;
        a0x = isB ? 0.f : q0;  a0y = isB ? q0 : 0.f;
        a1x = isB ? 0.f : q1;  a1y = isB ? q1 : 0.f;
    }

    // ---- steps v=1..14: depth-2 recurrence, P = wt (x) wm precomputed ----
#pragma unroll
    for (int v = 1; v <= 14; v++) {
        const bool ab = ((S >> v) ^ (S >> (v + 1))) & 1;
        const bool ae = (S >> v) & 1;
        const float wt0r = ab ? ct[v] : 1.f;
        const float wt1i = ab ? st[v] : 0.f;
        const float wm0r = ae ? cp[v] : 1.f;
        const float wm1i = ae ? sp[v] : 0.f;
        const float P00 = wt0r * wm0r;
        const float P01 = wt0r * wm1i;
        const float P10 = wt1i * wm0r;
        const float P11 = wt1i * wm1i;
        const float n0x =  P00 * a0x - P01 * a1y;
        const float n0y =  P00 * a0y + P01 * a1x;
        const float n1x = -P10 * a1y - P11 * a0x;
        const float n1y =  P10 * a1x - P11 * a0y;
        a0x = n0x; a0y = n0y; a1x = n1x; a1y = n1y;
    }

    // ---- close (mask bit 15), per-chain component select ----
    float val;
    {
        const bool ae = (S >> 15) & 1;
        const float wm0r = ae ? cp[15] : 1.f;
        const float wm1i = ae ? sp[15] : 0.f;
        const float r0 = isB ? wm1i : wm0r;
        const float r1 = isB ? wm0r : -wm1i;
        val = a0x * r0 + a1y * r1;       // A: resAx ; B: resBy
    }

    // combine chains: lane<16 holds A, partner lane^16 holds B
    const float other = __shfl_xor_sync(0xFFFFFFFFu, val, 16);
    if (!isB) {
        const bool ab15 = (S ^ (S >> 1) ^ (S >> 15)) & 1;   // b_15={0,1,15}
        const float w150r = ab15 ? ct[15] : 1.f;
        const float w151i = ab15 ? st[15] : 0.f;
        out[b * NQ + w] = w150r * val - w151i * other;
    }
}

extern "C" void kernel_launch(void* const* d_in, const int* in_sizes, int n_in,
                              void* d_out, int out_size) {
    const float* x   = (const float*)d_in[0];   // (32,16)
    const float* wts = (const float*)d_in[1];   // (2,16)
    if (n_in >= 2 && in_sizes[0] == 32 && in_sizes[1] == 512) {
        const float* tmp = x; x = wts; wts = tmp;  // defensive order swap
    }
    float* out = (float*)d_out;                 // (32,16) float32

    qnn_tm7<<<4, 32 * WARPS_PER_CTA>>>(x, wts, out);
}